// round 2
// baseline (speedup 1.0000x reference)
#include <cuda_runtime.h>

#define R_NUM 4096
#define L_NUM 32
#define C_NUM 512
#define CC    (C_NUM*C_NUM)
#define H_NUM 4
#define DH    128
#define NT    256
#define LD    516          // smem row stride (floats): 516 mod 32 = 4 -> conflict-free lane-per-row f4 reads
#define LN_EPS 1e-5f

struct Smem {
    float  X[L_NUM * LD];          // 66048 B
    float  A[L_NUM * LD];
    float  B[L_NUM * LD];
    float  S[H_NUM * L_NUM * L_NUM]; // 16384 B, overlaid with PMA vectors after SABs
    float4 Wp[2 * C_NUM];          // 16384 B: W panel, [kq][j] with kq in {0,1} (4 k each)
    float  red[32];
};

__device__ __forceinline__ float warp_sum(float v) {
#pragma unroll
    for (int o = 16; o; o >>= 1) v += __shfl_xor_sync(0xffffffffu, v, o);
    return v;
}

// Out[32][512] = Xs[32][512] @ Wg[512,512]^T + bg  (out[i][j] = sum_k Xs[i][k]*Wg[j][k])
// Xs/Out in smem with row stride LD. Wg/bg in global. Optional relu.
__device__ __noinline__ void gemm32(const float* __restrict__ Xs, const float* __restrict__ Wg,
                                    const float* __restrict__ bg, float* __restrict__ Out,
                                    float4* __restrict__ Wp, int tid, bool relu)
{
    const int rg = tid >> 6;   // 0..3 -> rows rg*8 .. rg*8+7 (uniform per warp)
    const int cg = tid & 63;   // cols cg + 64*jj (consecutive across lanes)
    float acc[8][8];
#pragma unroll
    for (int a = 0; a < 8; a++)
#pragma unroll
        for (int b = 0; b < 8; b++) acc[a][b] = 0.f;

    for (int k0 = 0; k0 < C_NUM; k0 += 8) {
        __syncthreads();
        // stage W panel: Wp[kq*512 + j] = float4 at Wg[j*512 + k0 + kq*4]
#pragma unroll
        for (int it = 0; it < 4; it++) {
            int idx = tid + it * NT;           // 0..1023
            int kq = idx >> 9, j = idx & 511;
            Wp[idx] = *reinterpret_cast<const float4*>(Wg + j * C_NUM + k0 + kq * 4);
        }
        __syncthreads();
#pragma unroll
        for (int kq = 0; kq < 2; kq++) {
            float4 xf[8];
#pragma unroll
            for (int ii = 0; ii < 8; ii++)
                xf[ii] = *reinterpret_cast<const float4*>(Xs + (rg * 8 + ii) * LD + k0 + kq * 4);
#pragma unroll
            for (int jj = 0; jj < 8; jj++) {
                float4 wf = Wp[kq * C_NUM + cg + 64 * jj];
#pragma unroll
                for (int ii = 0; ii < 8; ii++) {
                    acc[ii][jj] = fmaf(xf[ii].x, wf.x, acc[ii][jj]);
                    acc[ii][jj] = fmaf(xf[ii].y, wf.y, acc[ii][jj]);
                    acc[ii][jj] = fmaf(xf[ii].z, wf.z, acc[ii][jj]);
                    acc[ii][jj] = fmaf(xf[ii].w, wf.w, acc[ii][jj]);
                }
            }
        }
    }
#pragma unroll
    for (int jj = 0; jj < 8; jj++) {
        int j = cg + 64 * jj;
        float bj = bg[j];
#pragma unroll
        for (int ii = 0; ii < 8; ii++) {
            float v = acc[ii][jj] + bj;
            if (relu) v = fmaxf(v, 0.f);
            Out[(rg * 8 + ii) * LD + j] = v;
        }
    }
    __syncthreads();
}

// scores[h][i][j] = dot(Q[i, h*128:...], K[j, ...]) / sqrt(128); mask j>=ylen; softmax over j.
__device__ __noinline__ void sab_scores_softmax(const float* __restrict__ Q, const float* __restrict__ K,
                                                float* __restrict__ S, int ylen, int tid)
{
    const float scale = 0.08838834764831845f;  // 1/sqrt(128)
#pragma unroll
    for (int it = 0; it < 16; it++) {
        int idx = tid + it * NT;               // h*1024 + i*32 + j
        int h = idx >> 10, i = (idx >> 5) & 31, j = idx & 31;
        const float4* q4 = reinterpret_cast<const float4*>(Q + i * LD + h * DH);
        const float4* k4 = reinterpret_cast<const float4*>(K + j * LD + h * DH);
        float s0 = 0, s1 = 0, s2 = 0, s3 = 0;
#pragma unroll
        for (int d = 0; d < DH / 4; d++) {
            float4 a = q4[d], b = k4[d];
            s0 = fmaf(a.x, b.x, s0); s1 = fmaf(a.y, b.y, s1);
            s2 = fmaf(a.z, b.z, s2); s3 = fmaf(a.w, b.w, s3);
        }
        S[idx] = (s0 + s1 + s2 + s3) * scale;
    }
    __syncthreads();
    if (tid < H_NUM * L_NUM) {
        float* row = S + tid * L_NUM;          // tid = h*32 + i
        float mx = -1e30f;
        for (int j = 0; j < ylen; j++) mx = fmaxf(mx, row[j]);
        float sum = 0.f;
        for (int j = 0; j < L_NUM; j++) {
            float e = (j < ylen) ? __expf(row[j] - mx) : 0.f;
            row[j] = e; sum += e;
        }
        float inv = 1.f / sum;
        for (int j = 0; j < L_NUM; j++) row[j] *= inv;
    }
    __syncthreads();
}

// Out[i][c] = sum_j S[h(c)][i][j] * V[j][c]
__device__ __noinline__ void attn_v(const float* __restrict__ S, const float* __restrict__ V,
                                    float* __restrict__ Out, int ylen, int tid)
{
    const int rg = tid >> 6, cg = tid & 63;
    float acc[8][8];
#pragma unroll
    for (int a = 0; a < 8; a++)
#pragma unroll
        for (int b = 0; b < 8; b++) acc[a][b] = 0.f;

    for (int jk = 0; jk < ylen; jk++) {
        float vv[8];
#pragma unroll
        for (int jj = 0; jj < 8; jj++) vv[jj] = V[jk * LD + cg + 64 * jj];
        float sv[H_NUM][8];
#pragma unroll
        for (int h = 0; h < H_NUM; h++)
#pragma unroll
            for (int ii = 0; ii < 8; ii++)
                sv[h][ii] = S[h * (L_NUM * L_NUM) + (rg * 8 + ii) * L_NUM + jk];
#pragma unroll
        for (int jj = 0; jj < 8; jj++) {
            int h = jj >> 1;                  // h = (cg + 64*jj) >> 7, cg < 64
#pragma unroll
            for (int ii = 0; ii < 8; ii++)
                acc[ii][jj] = fmaf(sv[h][ii], vv[jj], acc[ii][jj]);
        }
    }
#pragma unroll
    for (int jj = 0; jj < 8; jj++)
#pragma unroll
        for (int ii = 0; ii < 8; ii++)
            Out[(rg * 8 + ii) * LD + cg + 64 * jj] = acc[ii][jj];
    __syncthreads();
}

// X[i] = LN(X[i] + (i<xm ? Y[i] : 0)) rowwise with gamma/beta
__device__ __noinline__ void sab_add_ln(float* __restrict__ X, const float* __restrict__ Y,
                                        const float* __restrict__ g, const float* __restrict__ b,
                                        int xm, int tid)
{
    const int w = tid >> 5, lane = tid & 31;
    for (int row = w; row < L_NUM; row += 8) {
        const float* yr = Y + row * LD;
        float* xr = X + row * LD;
        bool useY = row < xm;
        float s = 0.f, s2 = 0.f;
        for (int c = lane; c < C_NUM; c += 32) {
            float v = xr[c] + (useY ? yr[c] : 0.f);
            s += v; s2 += v * v;
        }
        s = warp_sum(s); s2 = warp_sum(s2);
        float mean = s * (1.f / C_NUM);
        float var = s2 * (1.f / C_NUM) - mean * mean;
        float rstd = rsqrtf(var + LN_EPS);
        for (int c = lane; c < C_NUM; c += 32) {
            float v = xr[c] + (useY ? yr[c] : 0.f);
            xr[c] = (v - mean) * rstd * g[c] + b[c];
        }
    }
    __syncthreads();
}

__device__ __noinline__ void mab_sab(Smem* sm,
    const float* Wq, const float* Wk, const float* Wv, const float* Wo, const float* ffW,
    const float* bq, const float* bk, const float* bv, const float* bo, const float* ffb,
    const float* g1, const float* b1, const float* g2, const float* b2,
    int ylen, int xm, int tid)
{
    gemm32(sm->X, Wq, bq, sm->A, sm->Wp, tid, false);             // Q -> A
    gemm32(sm->X, Wk, bk, sm->B, sm->Wp, tid, false);             // K -> B
    sab_scores_softmax(sm->A, sm->B, sm->S, ylen, tid);           // attn -> S
    gemm32(sm->X, Wv, bv, sm->B, sm->Wp, tid, false);             // V -> B (K dead)
    attn_v(sm->S, sm->B, sm->A, ylen, tid);                       // attn@V -> A (Q dead)
    gemm32(sm->A, Wo, bo, sm->B, sm->Wp, tid, false);             // O -> B
    sab_add_ln(sm->X, sm->B, g1, b1, xm, tid);                    // X = LN(X + mask(O))
    gemm32(sm->X, ffW, ffb, sm->A, sm->Wp, tid, true);            // relu FF -> A
    sab_add_ln(sm->X, sm->A, g2, b2, L_NUM, tid);                 // X = LN(X + FF)
}

// out[j] = sum_k xin[k]*Wg[j][k] + bg[j]   (xin: smem [512])
__device__ __noinline__ void vec_gemm(const float* __restrict__ xin, const float* __restrict__ Wg,
                                      const float* __restrict__ bg, float* __restrict__ out,
                                      int tid, bool relu)
{
    const float4* x4 = reinterpret_cast<const float4*>(xin);
    for (int j = tid; j < C_NUM; j += NT) {
        const float4* w4 = reinterpret_cast<const float4*>(Wg + j * C_NUM);
        float s0 = 0, s1 = 0, s2 = 0, s3 = 0;
#pragma unroll 8
        for (int kq = 0; kq < C_NUM / 4; kq++) {
            float4 w = w4[kq]; float4 x = x4[kq];
            s0 = fmaf(w.x, x.x, s0); s1 = fmaf(w.y, x.y, s1);
            s2 = fmaf(w.z, x.z, s2); s3 = fmaf(w.w, x.w, s3);
        }
        float v = s0 + s1 + s2 + s3 + bg[j];
        if (relu) v = fmaxf(v, 0.f);
        out[j] = v;
    }
    __syncthreads();
}

// x = LN(x + y) over a single 512-vector (block-wide)
__device__ __noinline__ void vec_add_ln(float* __restrict__ x, const float* __restrict__ y,
                                        const float* __restrict__ g, const float* __restrict__ b,
                                        float* __restrict__ red, int tid)
{
    float s = 0.f, s2 = 0.f;
    for (int c = tid; c < C_NUM; c += NT) {
        float v = x[c] + y[c]; s += v; s2 += v * v;
    }
    s = warp_sum(s); s2 = warp_sum(s2);
    int w = tid >> 5, lane = tid & 31;
    if (lane == 0) { red[w] = s; red[8 + w] = s2; }
    __syncthreads();
    if (tid == 0) {
        float ts = 0, ts2 = 0;
        for (int i = 0; i < 8; i++) { ts += red[i]; ts2 += red[8 + i]; }
        float mean = ts * (1.f / C_NUM);
        float var = ts2 * (1.f / C_NUM) - mean * mean;
        red[16] = mean; red[17] = rsqrtf(var + LN_EPS);
    }
    __syncthreads();
    float mean = red[16], rstd = red[17];
    for (int c = tid; c < C_NUM; c += NT) {
        float v = x[c] + y[c];
        x[c] = (v - mean) * rstd * g[c] + b[c];
    }
    __syncthreads();
}

// PMA attention: q (smem [512]) over K=sm->A [32,512], V=sm->B; attn out -> outv [512]
__device__ __noinline__ void pma_attn(Smem* sm, const float* __restrict__ q,
                                      float* __restrict__ psc, float* __restrict__ outv,
                                      int ylen, int tid)
{
    const float scale = 0.08838834764831845f;
    if (tid < H_NUM * L_NUM) {
        int h = tid >> 5, j = tid & 31;
        if (j < ylen) {
            const float4* q4 = reinterpret_cast<const float4*>(q + h * DH);
            const float4* k4 = reinterpret_cast<const float4*>(sm->A + j * LD + h * DH);
            float s0 = 0, s1 = 0, s2 = 0, s3 = 0;
#pragma unroll
            for (int d = 0; d < DH / 4; d++) {
                float4 a = q4[d], bb = k4[d];
                s0 = fmaf(a.x, bb.x, s0); s1 = fmaf(a.y, bb.y, s1);
                s2 = fmaf(a.z, bb.z, s2); s3 = fmaf(a.w, bb.w, s3);
            }
            psc[h * L_NUM + j] = (s0 + s1 + s2 + s3) * scale;
        }
    }
    __syncthreads();
    if (tid < H_NUM) {
        float* row = psc + tid * L_NUM;
        float mx = -1e30f;
        for (int j = 0; j < ylen; j++) mx = fmaxf(mx, row[j]);
        float sum = 0.f;
        for (int j = 0; j < ylen; j++) { float e = __expf(row[j] - mx); row[j] = e; sum += e; }
        float inv = 1.f / sum;
        for (int j = 0; j < ylen; j++) row[j] *= inv;
    }
    __syncthreads();
    for (int c = tid; c < C_NUM; c += NT) {
        int h = c >> 7;
        float s = 0.f;
        for (int j = 0; j < ylen; j++) s = fmaf(psc[h * L_NUM + j], sm->B[j * LD + c], s);
        outv[c] = s;
    }
    __syncthreads();
}

__global__ void __launch_bounds__(NT, 1)
rxn_set_transformer_kernel(
    const float* __restrict__ emb, const int* __restrict__ gidx, const int* __restrict__ glen,
    const float* __restrict__ Wq, const float* __restrict__ Wk, const float* __restrict__ Wv,
    const float* __restrict__ Wo, const float* __restrict__ ffW,
    const float* __restrict__ bq, const float* __restrict__ bk, const float* __restrict__ bv,
    const float* __restrict__ bo, const float* __restrict__ ffb,
    const float* __restrict__ g1, const float* __restrict__ b1,
    const float* __restrict__ g2, const float* __restrict__ b2,
    const float* __restrict__ pW, const float* __restrict__ pb,
    const float* __restrict__ seed, float* __restrict__ out)
{
    extern __shared__ char smem_raw[];
    Smem* sm = reinterpret_cast<Smem*>(smem_raw);
    const int tid = threadIdx.x;
    const int r = blockIdx.x;
    if (r >= R_NUM) return;

    int len = glen[r];
    if (len > L_NUM) len = L_NUM;
    if (len < 0) len = 0;

    // Gather + mask: X[i][c] = (i<len) ? emb[gidx[r,i]][c] : 0
#pragma unroll 4
    for (int it = 0; it < (L_NUM * C_NUM) / NT; it++) {
        int idx = tid + it * NT;
        int i = idx >> 9, c = idx & (C_NUM - 1);
        float v = 0.f;
        if (i < len) v = emb[(size_t)gidx[r * L_NUM + i] * C_NUM + c];
        sm->X[i * LD + c] = v;
    }
    __syncthreads();

    // Encoder SABs 0,1 (y_mask & x_mask = len)
    for (int blk = 0; blk < 2; blk++) {
        mab_sab(sm,
                Wq + blk * CC, Wk + blk * CC, Wv + blk * CC, Wo + blk * CC, ffW + blk * CC,
                bq + blk * C_NUM, bk + blk * C_NUM, bv + blk * C_NUM, bo + blk * C_NUM, ffb + blk * C_NUM,
                g1 + blk * C_NUM, b1 + blk * C_NUM, g2 + blk * C_NUM, b2 + blk * C_NUM,
                len, len, tid);
    }

    // y = relu(X @ pW^T + pb); copy back into X
    gemm32(sm->X, pW, pb, sm->A, sm->Wp, tid, true);
#pragma unroll 4
    for (int it = 0; it < (L_NUM * C_NUM) / NT; it++) {
        int idx = tid + it * NT;
        int i = idx >> 9, c = idx & (C_NUM - 1);
        sm->X[i * LD + c] = sm->A[i * LD + c];
    }
    __syncthreads();

    // PMA (block 2): seed (1 query) attends over X with y_mask=len, x_mask=None.
    // Small vectors overlaid in the (now free) score buffer S.
    float* psc = sm->S;            // 128 floats used
    float* xs  = sm->S + 512;      // current 1-token state
    float* vq  = sm->S + 1024;     // temp
    float* vt  = sm->S + 1536;     // temp
    for (int c = tid; c < C_NUM; c += NT) xs[c] = seed[c];
    __syncthreads();

    vec_gemm(xs, Wq + 2 * CC, bq + 2 * C_NUM, vq, tid, false);        // q
    gemm32(sm->X, Wk + 2 * CC, bk + 2 * C_NUM, sm->A, sm->Wp, tid, false); // K
    gemm32(sm->X, Wv + 2 * CC, bv + 2 * C_NUM, sm->B, sm->Wp, tid, false); // V
    pma_attn(sm, vq, psc, vt, len, tid);                              // attn out -> vt
    vec_gemm(vt, Wo + 2 * CC, bo + 2 * C_NUM, vq, tid, false);        // O -> vq
    vec_add_ln(xs, vq, g1 + 2 * C_NUM, b1 + 2 * C_NUM, sm->red, tid); // xs = LN(seed + O)
    vec_gemm(xs, ffW + 2 * CC, ffb + 2 * C_NUM, vt, tid, true);       // relu FF -> vt
    vec_add_ln(xs, vt, g2 + 2 * C_NUM, b2 + 2 * C_NUM, sm->red, tid);

    // Decoder SAB (block 3) on a single token: softmax over one key == 1, so
    // attention output == v. q/k projections are dead code and skipped.
    vec_gemm(xs, Wv + 3 * CC, bv + 3 * C_NUM, vq, tid, false);        // v
    vec_gemm(vq, Wo + 3 * CC, bo + 3 * C_NUM, vt, tid, false);        // O
    vec_add_ln(xs, vt, g1 + 3 * C_NUM, b1 + 3 * C_NUM, sm->red, tid);
    vec_gemm(xs, ffW + 3 * CC, ffb + 3 * C_NUM, vq, tid, true);       // relu FF
    vec_add_ln(xs, vq, g2 + 3 * C_NUM, b2 + 3 * C_NUM, sm->red, tid);

    // out[r] = xs (mean over 1 seed), zeroed if empty reaction
    for (int c = tid; c < C_NUM; c += NT)
        out[(size_t)r * C_NUM + c] = (len > 0) ? xs[c] : 0.f;
}

extern "C" void kernel_launch(void* const* d_in, const int* in_sizes, int n_in,
                              void* d_out, int out_size)
{
    const float* emb  = (const float*)d_in[0];
    const int*   gidx = (const int*)d_in[1];
    const int*   glen = (const int*)d_in[2];
    const float* Wq   = (const float*)d_in[3];
    const float* Wk   = (const float*)d_in[4];
    const float* Wv   = (const float*)d_in[5];
    const float* Wo   = (const float*)d_in[6];
    const float* ffW  = (const float*)d_in[7];
    const float* bq   = (const float*)d_in[8];
    const float* bk   = (const float*)d_in[9];
    const float* bv   = (const float*)d_in[10];
    const float* bo   = (const float*)d_in[11];
    const float* ffb  = (const float*)d_in[12];
    const float* g1   = (const float*)d_in[13];
    const float* b1   = (const float*)d_in[14];
    const float* g2   = (const float*)d_in[15];
    const float* b2   = (const float*)d_in[16];
    const float* pW   = (const float*)d_in[17];
    const float* pb   = (const float*)d_in[18];
    const float* seed = (const float*)d_in[19];

    (void)in_sizes; (void)n_in; (void)out_size;

    cudaFuncSetAttribute(rxn_set_transformer_kernel,
                         cudaFuncAttributeMaxDynamicSharedMemorySize,
                         (int)sizeof(Smem));

    rxn_set_transformer_kernel<<<R_NUM, NT, sizeof(Smem)>>>(
        emb, gidx, glen, Wq, Wk, Wv, Wo, ffW,
        bq, bk, bv, bo, ffb, g1, b1, g2, b2,
        pW, pb, seed, (float*)d_out);
}